// round 11
// baseline (speedup 1.0000x reference)
#include <cuda_runtime.h>
#include <cstdint>

// Problem constants (fixed shapes per reference)
#define NB      32
#define NC      64
#define NIN     10475
#define NOUT    2619
#define NNZ     (8 * NOUT)        // 20952
#define GPAIR   4                 // (b,c) pairs per block
#define NPAIR   (NB * NC)         // 2048
#define NBLK    (NPAIR / GPAIR)   // 512
#define THREADS 512
#define ROWS_PT 6                 // ceil(NOUT / THREADS)
#define QSIZE   2619              // quarter width (last quarter = 2618)
#define NQUART  4
#define MAXSLOT 16                // Poisson(2)/row-bucket; P(>=16) ~1e-10, guarded
#define RSTRIDE 2624              // smem floats per pair-row (16B multiple, >= 3+QSIZE)
#define BUFFLT  (GPAIR * RSTRIDE) // floats per quarter buffer (10496)
#define SMEM_BYTES (2 * BUFFLT * sizeof(float))   // 83,968 B -> 2 CTAs/SM

// Device scratch (zero-init at load; no runtime allocation)
__device__ int      d_cnt4[NQUART * NOUT];            // per-quarter counts
__device__ int2     d_ent4[NQUART * MAXSLOT * NOUT];  // slot-major {local col, val}
__device__ unsigned d_done;

// ---------------- ELL fill, bucketed by column quarter ----------------
__global__ void k_fill(const int* __restrict__ rows,
                       const int* __restrict__ cols,
                       const float* __restrict__ vals) {
    int k = blockIdx.x * blockDim.x + threadIdx.x;
    if (k < NNZ) {
        int r = rows[k];
        int c = cols[k];
        int q = c / QSIZE;                      // 0..3
        int lc = c - q * QSIZE;
        int slot = atomicAdd(&d_cnt4[q * NOUT + r], 1);
        if (slot < MAXSLOT)
            d_ent4[q * (MAXSLOT * NOUT) + slot * NOUT + r] =
                make_int2(lc, __float_as_int(vals[k]));
    }
}

// Stage one pair-row's quarter via cp.async: 16B bulk + 4B head/tail.
// src float-index S has S&3 alignment; element j lands at dstRow[(S&3)+j],
// making both sides of the 16B chunks aligned. (x base is 256B-aligned.)
__device__ __forceinline__ void stage_row(const float* __restrict__ src,
                                          uint32_t dstRowAddr, int ncols) {
    const int off  = (int)(((uintptr_t)src >> 2) & 3u);   // S & 3
    const int skew = (4 - off) & 3;                       // floats to 16B align
    uint32_t dbase = dstRowAddr + (uint32_t)(off * 4);
    // head
    for (int j = threadIdx.x; j < skew; j += THREADS)
        asm volatile("cp.async.ca.shared.global [%0], [%1], 4;"
                     :: "r"(dbase + (uint32_t)(j * 4)), "l"(src + j));
    // 16B bulk
    const int nb4 = (ncols - skew) >> 2;
    for (int t = threadIdx.x; t < nb4; t += THREADS) {
        int j = skew + t * 4;
        asm volatile("cp.async.cg.shared.global [%0], [%1], 16;"
                     :: "r"(dbase + (uint32_t)(j * 4)), "l"(src + j));
    }
    // tail
    const int rem = (ncols - skew) & 3;
    const int jt  = skew + nb4 * 4;
    for (int j = threadIdx.x; j < rem; j += THREADS)
        asm volatile("cp.async.ca.shared.global [%0], [%1], 4;"
                     :: "r"(dbase + (uint32_t)((jt + j) * 4)), "l"(src + jt + j));
}

__device__ __forceinline__ void issue_stage(const float* __restrict__ xg,
                                            int q, uint32_t sbuf) {
    const int ncols = (q == NQUART - 1) ? (NIN - (NQUART - 1) * QSIZE) : QSIZE;
    #pragma unroll
    for (int p = 0; p < GPAIR; p++)
        stage_row(xg + (size_t)p * NIN + q * QSIZE,
                  sbuf + (uint32_t)(p * RSTRIDE * 4), ncols);
    asm volatile("cp.async.commit_group;" ::: "memory");
}

// ---------------- Main SpMM kernel ----------------
// GPAIR=4, 2 CTAs/SM, 4 column-quarter phases, double-buffered via 16B
// cp.async (truly async: no register round-trip, staging never stalls the
// issuing warp). Planar smem rows with per-row alignment skew; gather is
// 4x LDS.32 per entry. Accumulators persist across quarters.
__global__ __launch_bounds__(THREADS, 2)
void k_main(const float* __restrict__ x, float* __restrict__ out) {
    extern __shared__ float smem[];       // 2 * BUFFLT floats
    const int tid = threadIdx.x;
    const int pb  = blockIdx.x * GPAIR;
    const float* __restrict__ xg = x + (size_t)pb * NIN;

    uint32_t sb0 = (uint32_t)__cvta_generic_to_shared(smem);
    uint32_t sb1 = sb0 + BUFFLT * 4u;

    float4 acc[ROWS_PT];
    #pragma unroll
    for (int i = 0; i < ROWS_PT; i++) acc[i] = make_float4(0.f, 0.f, 0.f, 0.f);

    issue_stage(xg, 0, sb0);

    #pragma unroll 1
    for (int q = 0; q < NQUART; q++) {
        if (q + 1 < NQUART)
            issue_stage(xg, q + 1, ((q + 1) & 1) ? sb1 : sb0);

        if (q < NQUART - 1) asm volatile("cp.async.wait_group 1;" ::: "memory");
        else                asm volatile("cp.async.wait_group 0;" ::: "memory");
        __syncthreads();   // quarter q staged & visible

        // per-row smem base (element 0) incl. alignment skew for this quarter
        const float* __restrict__ buf = (q & 1) ? (smem + BUFFLT) : smem;
        int base[GPAIR];
        #pragma unroll
        for (int p = 0; p < GPAIR; p++)
            base[p] = p * RSTRIDE + (int)((((size_t)(pb + p) * NIN) + (size_t)q * QSIZE) & 3);

        const int*  __restrict__ cnt = d_cnt4 + q * NOUT;
        const int2* __restrict__ tbl = d_ent4 + q * (MAXSLOT * NOUT);

        int c[ROWS_PT];
        int cmax = 0;
        #pragma unroll
        for (int i = 0; i < ROWS_PT; i++) {
            int r = tid + i * THREADS;
            c[i] = (r < NOUT) ? min(cnt[r], MAXSLOT) : 0;
            cmax = max(cmax, c[i]);
        }

        for (int k = 0; k < cmax; k++) {
            const int2* __restrict__ ek = tbl + k * NOUT;
            #pragma unroll
            for (int i = 0; i < ROWS_PT; i++) {
                if (k < c[i]) {
                    int2 e = __ldg(ek + tid + i * THREADS);
                    float v = __int_as_float(e.y);
                    acc[i].x = fmaf(v, buf[base[0] + e.x], acc[i].x);
                    acc[i].y = fmaf(v, buf[base[1] + e.x], acc[i].y);
                    acc[i].z = fmaf(v, buf[base[2] + e.x], acc[i].z);
                    acc[i].w = fmaf(v, buf[base[3] + e.x], acc[i].w);
                }
            }
        }
        __syncthreads();   // buf fully read before it refills at q+2
    }

    // ---- coalesced stores: 4 output streams x 6 rows ----
    float* __restrict__ o0 = out + (size_t)pb * NOUT;
    #pragma unroll
    for (int i = 0; i < ROWS_PT; i++) {
        int r = tid + i * THREADS;
        if (r < NOUT) {
            o0[r]            = acc[i].x;
            o0[NOUT + r]     = acc[i].y;
            o0[2 * NOUT + r] = acc[i].z;
            o0[3 * NOUT + r] = acc[i].w;
        }
    }

    // ---- last finished CTA resets counts for the next graph replay ----
    __shared__ unsigned s_last;
    if (tid == 0) {
        __threadfence();
        s_last = (atomicAdd(&d_done, 1u) == (unsigned)(gridDim.x - 1));
    }
    __syncthreads();
    if (s_last) {
        for (int i = tid; i < NQUART * NOUT; i += THREADS) d_cnt4[i] = 0;
        if (tid == 0) d_done = 0;
    }
}

// ---------------- launch ----------------
extern "C" void kernel_launch(void* const* d_in, const int* in_sizes, int n_in,
                              void* d_out, int out_size) {
    const float* x      = (const float*)d_in[0];
    const int*   M_rows = (const int*)d_in[1];
    const int*   M_cols = (const int*)d_in[2];
    const float* M_vals = (const float*)d_in[3];
    float* out = (float*)d_out;

    (void)in_sizes; (void)n_in; (void)out_size;

    cudaFuncSetAttribute(k_main, cudaFuncAttributeMaxDynamicSharedMemorySize,
                         (int)SMEM_BYTES);

    k_fill<<<(NNZ + 255) / 256, 256>>>(M_rows, M_cols, M_vals);
    k_main<<<NBLK, THREADS, SMEM_BYTES>>>(x, out);
}

// round 12
// speedup vs baseline: 1.1289x; 1.1289x over previous
#include <cuda_runtime.h>
#include <cstdint>

// Problem constants (fixed shapes per reference)
#define NB      32
#define NC      64
#define NIN     10475
#define NOUT    2619
#define NNZ     (8 * NOUT)        // 20952
#define GPAIR   4                 // (b,c) pairs per block
#define NPAIR   (NB * NC)         // 2048
#define NBLK    (NPAIR / GPAIR)   // 512
#define THREADS 512
#define WSTAGE  128               // producer threads (4 warps)
#define WCOMP   384               // consumer threads (12 warps)
#define ROWS_PT 7                 // ceil(NOUT / WCOMP)
#define QSIZE   2619              // quarter width (last quarter = 2618)
#define NQUART  4
#define MAXSLOT 16                // Poisson(2)/row-bucket; P(>=16) ~1e-10, guarded
#define QBUF    2620              // padded float4 granules per buffer
#define SMEM_BYTES (2 * QBUF * sizeof(float4))   // 83,840 B -> 2 CTAs/SM

// Device scratch (zero-init at load; no runtime allocation)
__device__ int      d_cnt4[NQUART * NOUT];            // per-quarter counts
__device__ int2     d_ent4[NQUART * MAXSLOT * NOUT];  // slot-major {local col, val}
__device__ unsigned d_done;

// ---------------- ELL fill, bucketed by column quarter ----------------
__global__ void k_fill(const int* __restrict__ rows,
                       const int* __restrict__ cols,
                       const float* __restrict__ vals) {
    int k = blockIdx.x * blockDim.x + threadIdx.x;
    if (k < NNZ) {
        int r = rows[k];
        int c = cols[k];
        int q = c / QSIZE;                      // 0..3
        int lc = c - q * QSIZE;
        int slot = atomicAdd(&d_cnt4[q * NOUT + r], 1);
        if (slot < MAXSLOT)
            d_ent4[q * (MAXSLOT * NOUT) + slot * NOUT + r] =
                make_int2(lc, __float_as_int(vals[k]));
    }
}

// Stage one column-quarter of the block's 4 x-rows into a smem buffer as
// float4-interleaved granules: buf[j] = {x[p0..p3][qbase+j]}.
// 4 coalesced LDG.32 streams -> one conflict-free STS.128 per granule.
__device__ __forceinline__ void stage_quarter(const float* __restrict__ xg,
                                              int q, float4* __restrict__ buf,
                                              int t, int nthreads) {
    const int ncols = (q == NQUART - 1) ? (NIN - (NQUART - 1) * QSIZE) : QSIZE;
    const float* __restrict__ base = xg + q * QSIZE;
    for (int j = t; j < ncols; j += nthreads) {
        buf[j] = make_float4(__ldg(base + j),
                             __ldg(base + j + NIN),
                             __ldg(base + j + 2 * NIN),
                             __ldg(base + j + 3 * NIN));
    }
}

// ---------------- Main SpMM kernel (warp-specialized pipeline) ----------------
// GPAIR=4, 512 threads, 2 CTAs/SM. Warps 0-3 are producers: they stage
// quarter q+1 (LDG->STS; their DRAM stalls are off the critical path).
// Warps 4-15 are consumers: float4-interleaved gather (1 LDS.128 per entry
// serves 4 pairs), 7 lockstep row-chains per thread. Double-buffered
// quarters; __syncthreads() separates phases. Accumulators persist.
__global__ __launch_bounds__(THREADS, 2)
void k_main(const float* __restrict__ x, float* __restrict__ out) {
    extern __shared__ float4 smem[];      // 2 * QBUF granules
    const int tid = threadIdx.x;
    const int pb  = blockIdx.x * GPAIR;
    const float* __restrict__ xg = x + (size_t)pb * NIN;

    const bool producer = (tid < WSTAGE);
    const int  tc = tid - WSTAGE;         // consumer lane id (0..WCOMP-1)

    float4 acc[ROWS_PT];
    #pragma unroll
    for (int i = 0; i < ROWS_PT; i++) acc[i] = make_float4(0.f, 0.f, 0.f, 0.f);

    // quarter 0 staged by ALL threads (fast cold start)
    stage_quarter(xg, 0, smem, tid, THREADS);
    __syncthreads();

    #pragma unroll 1
    for (int q = 0; q < NQUART; q++) {
        if (producer) {
            // ---- stage next quarter into the idle buffer ----
            if (q + 1 < NQUART)
                stage_quarter(xg, q + 1,
                              ((q + 1) & 1) ? (smem + QBUF) : smem,
                              tid, WSTAGE);
        } else {
            // ---- consume quarter q ----
            const float4* __restrict__ sm4 = (q & 1) ? (smem + QBUF) : smem;
            const int*  __restrict__ cnt = d_cnt4 + q * NOUT;
            const int2* __restrict__ tbl = d_ent4 + q * (MAXSLOT * NOUT);

            int c[ROWS_PT];
            int cmax = 0;
            #pragma unroll
            for (int i = 0; i < ROWS_PT; i++) {
                int r = tc + i * WCOMP;
                c[i] = (r < NOUT) ? min(cnt[r], MAXSLOT) : 0;
                cmax = max(cmax, c[i]);
            }

            for (int k = 0; k < cmax; k++) {
                const int2* __restrict__ ek = tbl + k * NOUT;
                #pragma unroll
                for (int i = 0; i < ROWS_PT; i++) {
                    if (k < c[i]) {
                        int2 e = __ldg(ek + tc + i * WCOMP);
                        float v  = __int_as_float(e.y);
                        float4 xv = sm4[e.x];
                        acc[i].x = fmaf(v, xv.x, acc[i].x);
                        acc[i].y = fmaf(v, xv.y, acc[i].y);
                        acc[i].z = fmaf(v, xv.z, acc[i].z);
                        acc[i].w = fmaf(v, xv.w, acc[i].w);
                    }
                }
            }
        }
        __syncthreads();   // quarter q consumed; quarter q+1 staged
    }

    // ---- coalesced stores by consumers: 4 output streams x 7 rows ----
    if (!producer) {
        float* __restrict__ o0 = out + (size_t)pb * NOUT;
        #pragma unroll
        for (int i = 0; i < ROWS_PT; i++) {
            int r = tc + i * WCOMP;
            if (r < NOUT) {
                o0[r]            = acc[i].x;
                o0[NOUT + r]     = acc[i].y;
                o0[2 * NOUT + r] = acc[i].z;
                o0[3 * NOUT + r] = acc[i].w;
            }
        }
    }

    // ---- last finished CTA resets counts for the next graph replay ----
    __shared__ unsigned s_last;
    if (tid == 0) {
        __threadfence();
        s_last = (atomicAdd(&d_done, 1u) == (unsigned)(gridDim.x - 1));
    }
    __syncthreads();
    if (s_last) {
        for (int i = tid; i < NQUART * NOUT; i += THREADS) d_cnt4[i] = 0;
        if (tid == 0) d_done = 0;
    }
}

// ---------------- launch ----------------
extern "C" void kernel_launch(void* const* d_in, const int* in_sizes, int n_in,
                              void* d_out, int out_size) {
    const float* x      = (const float*)d_in[0];
    const int*   M_rows = (const int*)d_in[1];
    const int*   M_cols = (const int*)d_in[2];
    const float* M_vals = (const float*)d_in[3];
    float* out = (float*)d_out;

    (void)in_sizes; (void)n_in; (void)out_size;

    cudaFuncSetAttribute(k_main, cudaFuncAttributeMaxDynamicSharedMemorySize,
                         (int)SMEM_BYTES);

    k_fill<<<(NNZ + 255) / 256, 256>>>(M_rows, M_cols, M_vals);
    k_main<<<NBLK, THREADS, SMEM_BYTES>>>(x, out);
}